// round 12
// baseline (speedup 1.0000x reference)
#include <cuda_runtime.h>
#include <math.h>

#define SEQ   512
#define BATCH 64
#define EMB   300
#define HID   512
#define GATES 2048   // 4*HID
#define NTAG  12
#define NEGV  (-10000.0f)
#define START_TAG 10
#define STOP_TAG  11

// ---------------- scratch (device globals; no allocation) ----------------
__device__ float g_xw[2][SEQ][GATES][BATCH];   // pre-activations x@W_ih.T+b
__device__ __align__(256) float g_hf[SEQ][HID][BATCH];   // forward hidden states
__device__ __align__(256) float g_hb[SEQ][HID][BATCH];   // backward hidden (scan order)
__device__ __align__(256) float g_hinit[2][HID][BATCH];  // transposed h0
__device__ float g_Wt_ih[2][EMB][GATES];       // W_ih transposed [e][j]
__device__ float g_Wout_t[2 * HID][NTAG];      // W_out transposed [k][t]
__device__ float g_feats[SEQ][BATCH][NTAG];
__device__ float g_crf_part[8];
__device__ unsigned g_cnt2[2];
__device__ unsigned g_gen2[2];

// ---------------- f32x2 helpers ----------------
__device__ __forceinline__ unsigned long long splat2(float x) {
    unsigned long long r; unsigned u = __float_as_uint(x);
    asm("mov.b64 %0, {%1, %1};" : "=l"(r) : "r"(u));
    return r;
}
__device__ __forceinline__ void ffma2(unsigned long long& d,
                                      unsigned long long a,
                                      unsigned long long b) {
    asm("fma.rn.f32x2 %0, %1, %2, %0;" : "+l"(d) : "l"(a), "l"(b));
}
__device__ __forceinline__ unsigned long long addf2(unsigned long long a,
                                                    unsigned long long b) {
    unsigned long long r;
    asm("add.rn.f32x2 %0, %1, %2;" : "=l"(r) : "l"(a), "l"(b));
    return r;
}
__device__ __forceinline__ float2 unpack2(unsigned long long v) {
    unsigned lo, hi;
    asm("mov.b64 {%0, %1}, %2;" : "=r"(lo), "=r"(hi) : "l"(v));
    float2 f; f.x = __uint_as_float(lo); f.y = __uint_as_float(hi);
    return f;
}
__device__ __forceinline__ float sigf(float x) { return 1.f / (1.f + __expf(-x)); }
__device__ __forceinline__ float tanhfast(float x) { return 2.f / (1.f + __expf(-2.f * x)) - 1.f; }

__device__ __forceinline__ unsigned ld_acq(const unsigned* p) {
    unsigned v;
    asm volatile("ld.acquire.gpu.global.u32 %0, [%1];" : "=r"(v) : "l"(p) : "memory");
    return v;
}

// ---------------- TMA bulk-copy / mbarrier helpers ----------------
__device__ __forceinline__ void mbar_init(unsigned addr, unsigned cnt) {
    asm volatile("mbarrier.init.shared.b64 [%0], %1;" :: "r"(addr), "r"(cnt) : "memory");
}
__device__ __forceinline__ void mbar_expect_tx(unsigned addr, unsigned bytes) {
    asm volatile("mbarrier.arrive.expect_tx.shared.b64 _, [%0], %1;"
                 :: "r"(addr), "r"(bytes) : "memory");
}
__device__ __forceinline__ void bulk_g2s(unsigned dst, const void* src,
                                         unsigned bytes, unsigned mbar) {
    asm volatile("cp.async.bulk.shared::cta.global.mbarrier::complete_tx::bytes "
                 "[%0], [%1], %2, [%3];"
                 :: "r"(dst), "l"(src), "r"(bytes), "r"(mbar) : "memory");
}
__device__ __forceinline__ void mbar_wait(unsigned addr, unsigned parity) {
    asm volatile(
        "{\n\t.reg .pred P;\n\t"
        "LAB_WAIT_%=:\n\t"
        "mbarrier.try_wait.parity.acquire.cta.shared::cta.b64 P, [%0], %1, 0x989680;\n\t"
        "@P bra.uni LAB_DONE_%=;\n\t"
        "bra.uni LAB_WAIT_%=;\n\t"
        "LAB_DONE_%=:\n\t}"
        :: "r"(addr), "r"(parity) : "memory");
}

// ---------------- prep: transposes + state init + barrier reset ----------------
__global__ void prep_kernel(const float* Wif, const float* Wib, const float* h0,
                            const float* Wout) {
    if (blockIdx.x == 0 && threadIdx.x < 2) {
        g_cnt2[threadIdx.x] = 0;
        g_gen2[threadIdx.x] = 0;
    }
    const int N_IH = 2 * EMB * GATES;
    const int N_H  = 2 * HID * BATCH;
    const int N_WO = NTAG * 2 * HID;
    const int total = N_IH + N_H + N_WO;
    for (int idx = blockIdx.x * blockDim.x + threadIdx.x; idx < total;
         idx += gridDim.x * blockDim.x) {
        int i = idx;
        if (i < N_IH) {
            int d = i / (EMB * GATES);
            int r = i % (EMB * GATES);
            int e = r / GATES, j = r % GATES;
            const float* W = d ? Wib : Wif;
            g_Wt_ih[d][e][j] = W[j * EMB + e];
        } else if ((i -= N_IH) < N_H) {
            int d = i / (HID * BATCH);
            int r = i % (HID * BATCH);
            int u = r / BATCH, b = r % BATCH;
            g_hinit[d][u][b] = h0[(d * BATCH + b) * HID + u];
        } else {
            i -= N_H;
            int k = i / NTAG, t = i % NTAG;
            g_Wout_t[k][t] = Wout[t * (2 * HID) + k];
        }
    }
}

// ---------------- input GEMM (f32x2) ----------------
__global__ __launch_bounds__(256)
void xw_gemm(const int* __restrict__ tokens,
             const float* __restrict__ W_emb,
             const float* __restrict__ b_f,
             const float* __restrict__ b_b) {
    int dir = blockIdx.z;
    int s   = blockIdx.y;
    int n0  = blockIdx.x * 128;
    __shared__ float As[16][64];
    __shared__ float Bs[16][128];
    __shared__ int   tokS[64];
    int tid = threadIdx.x;
    if (tid < 64) {
        int srow = dir ? (SEQ - 1 - s) : s;
        tokS[tid] = tokens[tid * SEQ + srow];
    }
    __syncthreads();
    int c0 = (tid >> 3) * 4;
    int b0 = (tid & 7) * 8;
    unsigned long long acc[4][4] = {};
    for (int k0 = 0; k0 < 304; k0 += 16) {
        {
            int b = tid & 63, kk4 = (tid >> 6) * 4;
            int k = k0 + kk4;
            float4 v = {0.f, 0.f, 0.f, 0.f};
            if (k + 3 < EMB)
                v = *(const float4*)(W_emb + (size_t)tokS[b] * EMB + k);
            As[kk4 + 0][b] = v.x;
            As[kk4 + 1][b] = v.y;
            As[kk4 + 2][b] = v.z;
            As[kk4 + 3][b] = v.w;
        }
#pragma unroll
        for (int r = 0; r < 2; r++) {
            int idx = tid + 256 * r;
            int kk = idx >> 5, cg = idx & 31;
            float4 w = {0.f, 0.f, 0.f, 0.f};
            if (k0 + kk < EMB)
                w = *(const float4*)&g_Wt_ih[dir][k0 + kk][n0 + cg * 4];
            *(float4*)&Bs[kk][cg * 4] = w;
        }
        __syncthreads();
#pragma unroll
        for (int kk = 0; kk < 16; kk++) {
            float4 wv = *(const float4*)&Bs[kk][c0];
            unsigned long long w0 = splat2(wv.x), w1 = splat2(wv.y);
            unsigned long long w2 = splat2(wv.z), w3 = splat2(wv.w);
            ulonglong2 xA = *(const ulonglong2*)&As[kk][b0];
            ulonglong2 xB = *(const ulonglong2*)&As[kk][b0 + 4];
            ffma2(acc[0][0], xA.x, w0); ffma2(acc[0][1], xA.y, w0);
            ffma2(acc[0][2], xB.x, w0); ffma2(acc[0][3], xB.y, w0);
            ffma2(acc[1][0], xA.x, w1); ffma2(acc[1][1], xA.y, w1);
            ffma2(acc[1][2], xB.x, w1); ffma2(acc[1][3], xB.y, w1);
            ffma2(acc[2][0], xA.x, w2); ffma2(acc[2][1], xA.y, w2);
            ffma2(acc[2][2], xB.x, w2); ffma2(acc[2][3], xB.y, w2);
            ffma2(acc[3][0], xA.x, w3); ffma2(acc[3][1], xA.y, w3);
            ffma2(acc[3][2], xB.x, w3); ffma2(acc[3][3], xB.y, w3);
        }
        __syncthreads();
    }
    const float* bias = dir ? b_b : b_f;
#pragma unroll
    for (int cc = 0; cc < 4; cc++) {
        int j = n0 + c0 + cc;
        float bv = bias[j];
        float2 p0 = unpack2(acc[cc][0]), p1 = unpack2(acc[cc][1]);
        float2 p2 = unpack2(acc[cc][2]), p3 = unpack2(acc[cc][3]);
        float4 o0 = {p0.x + bv, p0.y + bv, p1.x + bv, p1.y + bv};
        float4 o1 = {p2.x + bv, p2.y + bv, p3.x + bv, p3.y + bv};
        *(float4*)&g_xw[dir][s][j][b0] = o0;
        *(float4*)&g_xw[dir][s][j][b0 + 4] = o1;
    }
}

// ---------------- persistent fused BiLSTM: BOTH directions per block -----------
// 128 blocks x 256 thr. Block = 4 units x 4 gates (16 cols) of fwd AND bwd.
// Per step: fwd phase (compute, write h_f, ARRIVE) then bwd phase; each
// direction's barrier wait + h round-trip hides under the other's compute.
// Thread = (kg 0/1, cp 0..7, bq 0..15): 2 cols x 4 batch x 256 k.
__global__ __launch_bounds__(256, 1)
void lstm_persistent(const float* __restrict__ Whf, const float* __restrict__ Whb,
                     const float* __restrict__ c0in) {
    extern __shared__ float smem[];
    float2* sW = (float2*)smem;               // [2 dir][8 cp][513] float2 = 65,664 B
    float*  sH = smem + 16 * 513 * 2;         // h buffer 512 k x 64 b = 131,072 B
    __shared__ __align__(8) unsigned long long s_mbar[2];

    int tid = threadIdx.x;
    int bid = blockIdx.x;
    int u0  = bid * 4;                        // 4 hidden units (both dirs)

    unsigned mb0 = (unsigned)__cvta_generic_to_shared(&s_mbar[0]);
    unsigned mb1 = (unsigned)__cvta_generic_to_shared(&s_mbar[1]);
    unsigned sH_addr = (unsigned)__cvta_generic_to_shared(sH);
    if (tid == 0) {
        mbar_init(mb0, 1);
        mbar_init(mb1, 1);
    }

    // stage W for both dirs: sW[(d*8+cp)][k] = (W[col 2cp][k], W[col 2cp+1][k])
    // col c (0..15): gate = c>>2, unit = c&3; j = gate*HID + u0 + unit
    for (int l = tid; l < 2 * 8 * 512; l += 256) {
        int dw = l >> 12;
        int rem = l & 4095;
        int cp_ = rem >> 9, k = rem & 511;
        int ca = cp_ * 2, cb = ca + 1;
        int ja = (ca >> 2) * HID + u0 + (ca & 3);
        int jb = (cb >> 2) * HID + u0 + (cb & 3);
        const float* W = dw ? Whb : Whf;
        float2 v;
        v.x = W[ja * HID + k];
        v.y = W[jb * HID + k];
        sW[(dw * 8 + cp_) * 513 + k] = v;
    }

    int kg = tid >> 7;                        // k-half 0/1 (256 k each)
    int lo = tid & 127;
    int cp = lo >> 4;                         // col-pair 0..7
    int c0i = cp * 2, c1i = c0i + 1;
    int b0 = (lo & 15) * 4;                   // batch base (4 per thread)
    int k0 = kg * 256;
    unsigned my_mbar = kg ? mb1 : mb0;

    // cell state for both dirs: 1 elem/thread each
    float cst[2];
    {
        int uu = (tid >> 6) & 3, b = tid & 63;
        cst[0] = c0in[(0 * BATCH + b) * HID + (u0 + uu)];
        cst[1] = c0in[(1 * BATCH + b) * HID + (u0 + uu)];
    }
    __syncthreads();

    int j0 = (c0i >> 2) * HID + u0 + (c0i & 3);
    int j1 = (c1i >> 2) * HID + u0 + (c1i & 3);

    for (int s = 0; s < SEQ; s++) {
#pragma unroll 1
        for (int ph = 0; ph < 2; ph++) {      // 0 = fwd, 1 = bwd
            const int d = ph;
            const float* hprev = (s == 0) ? &g_hinit[d][0][0]
                                          : (d ? &g_hb[s - 1][0][0] : &g_hf[s - 1][0][0]);
            float* hout = d ? &g_hb[s][0][0] : &g_hf[s][0][0];
            const float2* wrow = sW + (d * 8 + cp) * 513;

            // tid0: wait this direction's previous barrier (hidden: a full
            // other-direction phase has elapsed since arrivals), then TMA h.
            if (tid == 0) {
                if (s > 0) {
                    unsigned g;
                    do { g = ld_acq(&g_gen2[d]); } while (g < (unsigned)s);
                }
                asm volatile("fence.proxy.async;" ::: "memory");
                mbar_expect_tx(mb0, 65536);
                bulk_g2s(sH_addr, hprev, 65536, mb0);
                mbar_expect_tx(mb1, 65536);
                bulk_g2s(sH_addr + 65536, hprev + 16384, 65536, mb1);
            }

            // hoist xw loads (kg==0 threads consume them in reduce)
            float4 x0, x1;
            if (kg == 0) {
                x0 = *(const float4*)&g_xw[d][s][j0][b0];
                x1 = *(const float4*)&g_xw[d][s][j1][b0];
            }

            // wait this k-half's chunk (parity = ph: mbar completes 2x/step)
            mbar_wait(my_mbar, ph);

            // compute this k-half: 128 iters of 2 k
            unsigned long long a00 = 0, a01 = 0, a10 = 0, a11 = 0;
#pragma unroll 8
            for (int kk = k0; kk < k0 + 256; kk += 2) {
                float2 wA = wrow[kk];
                float2 wB = wrow[kk + 1];
                unsigned long long hA0 = *(const unsigned long long*)(sH + kk * BATCH + b0);
                unsigned long long hA1 = *(const unsigned long long*)(sH + kk * BATCH + b0 + 2);
                unsigned long long hB0 = *(const unsigned long long*)(sH + (kk + 1) * BATCH + b0);
                unsigned long long hB1 = *(const unsigned long long*)(sH + (kk + 1) * BATCH + b0 + 2);
                unsigned long long wa0 = splat2(wA.x), wa1 = splat2(wA.y);
                unsigned long long wb0 = splat2(wB.x), wb1 = splat2(wB.y);
                ffma2(a00, hA0, wa0); ffma2(a01, hA1, wa0);
                ffma2(a10, hA0, wa1); ffma2(a11, hA1, wa1);
                ffma2(a00, hB0, wb0); ffma2(a01, hB1, wb0);
                ffma2(a10, hB0, wb1); ffma2(a11, hB1, wb1);
            }
            __syncthreads();   // all reads of sH done

            // K-split reduce: kg1 parks 4 u64 at slot lo (park aliases sH[0,4KB))
            if (kg == 1) {
                ulonglong2* pp = (ulonglong2*)((unsigned long long*)sH + (size_t)lo * 4);
                pp[0] = make_ulonglong2(a00, a01);
                pp[1] = make_ulonglong2(a10, a11);
            }
            __syncthreads();

            float* sG = sH + 2048;             // gates region (beyond 4KB park)
            if (kg == 0) {
                const ulonglong2* pp =
                    (const ulonglong2*)((unsigned long long*)sH + (size_t)lo * 4);
                ulonglong2 v0 = pp[0], v1 = pp[1];
                a00 = addf2(a00, v0.x); a01 = addf2(a01, v0.y);
                a10 = addf2(a10, v1.x); a11 = addf2(a11, v1.y);
                float2 p0 = unpack2(a00), p1 = unpack2(a01);
                float2 q0 = unpack2(a10), q1 = unpack2(a11);
                float4 o0 = {p0.x + x0.x, p0.y + x0.y, p1.x + x0.z, p1.y + x0.w};
                float4 o1 = {q0.x + x1.x, q0.y + x1.y, q1.x + x1.z, q1.y + x1.w};
                *(float4*)(sG + c0i * 68 + b0) = o0;
                *(float4*)(sG + c1i * 68 + b0) = o1;
            }
            __syncthreads();

            // pointwise: 1 elem/thread (4 units x 64 batch); c in registers
            {
                int uu = (tid >> 6) & 3, b = tid & 63;
                float gi = sG[(0 + uu) * 68 + b];
                float gf = sG[(4 + uu) * 68 + b];
                float gg = sG[(8 + uu) * 68 + b];
                float go = sG[(12 + uu) * 68 + b];
                float iv = sigf(gi), fv = sigf(gf), ov = sigf(go);
                float c = fv * cst[ph] + iv * tanhfast(gg);
                cst[ph] = c;
                hout[(u0 + uu) * BATCH + b] = ov * tanhfast(c);
            }
            __syncthreads();   // h writes issued; sG reads done (TMA may reuse sH)

            // ARRIVE on this direction's barrier (non-blocking); release writes
            if (s < SEQ - 1 && tid == 0) {
                unsigned target = (unsigned)(s + 1);
                unsigned prev;
                asm volatile("atom.acq_rel.gpu.global.add.u32 %0, [%1], 1;"
                             : "=r"(prev) : "l"(&g_cnt2[d]) : "memory");
                if (prev == 127) {
                    asm volatile("st.relaxed.gpu.global.u32 [%0], %1;"
                                 :: "l"(&g_cnt2[d]), "r"(0u) : "memory");
                    asm volatile("st.release.gpu.global.u32 [%0], %1;"
                                 :: "l"(&g_gen2[d]), "r"(target) : "memory");
                }
            }
        }
    }
}

// ---------------- feats: K-split, 12 independent chains per thread ----------------
__global__ __launch_bounds__(256)
void feats_kernel(const float* __restrict__ b_out) {
    int s = blockIdx.x;
    int tid = threadIdx.x;
    int b = tid & 63;
    int slice = tid >> 6;
    __shared__ float sred[256][NTAG];
    float a[NTAG];
#pragma unroll
    for (int t = 0; t < NTAG; t++) a[t] = 0.f;

    int base = slice * 256;
    const float* hbase = (base < HID) ? &g_hf[s][base][0]
                                      : &g_hb[SEQ - 1 - s][base - HID][0];
#pragma unroll 4
    for (int k = 0; k < 256; k++) {
        float h = hbase[k * BATCH + b];
        int kg = base + k;
        float4 w0 = *(const float4*)&g_Wout_t[kg][0];
        float4 w1 = *(const float4*)&g_Wout_t[kg][4];
        float4 w2 = *(const float4*)&g_Wout_t[kg][8];
        a[0] += h * w0.x;  a[1] += h * w0.y;  a[2]  += h * w0.z;  a[3]  += h * w0.w;
        a[4] += h * w1.x;  a[5] += h * w1.y;  a[6]  += h * w1.z;  a[7]  += h * w1.w;
        a[8] += h * w2.x;  a[9] += h * w2.y;  a[10] += h * w2.z;  a[11] += h * w2.w;
    }
#pragma unroll
    for (int t = 0; t < NTAG; t++) sred[tid][t] = a[t];
    __syncthreads();
    if (tid < 64) {
#pragma unroll
        for (int t = 0; t < NTAG; t++) {
            float v = b_out[t] + sred[tid][t] + sred[64 + tid][t]
                    + sred[128 + tid][t] + sred[192 + tid][t];
            g_feats[s][tid][t] = v;
        }
    }
}

// ---------------- CRF forward: 8 blocks x 8 batches, feats prefetch ----------------
__global__ __launch_bounds__(96)
void crf_kernel(const int* __restrict__ lengths,
                const float* __restrict__ trans) {
    __shared__ float alpha[8][NTAG];
    __shared__ float tr[NTAG][NTAG];
    __shared__ float termS[8][NTAG];
    int tid = threadIdx.x;
    int b = tid / NTAG, t = tid % NTAG;
    int bg = blockIdx.x * 8 + b;
    for (int l = tid; l < NTAG * NTAG; l += 96)
        tr[l / NTAG][l % NTAG] = trans[l];
    alpha[b][t] = (t == START_TAG) ? 0.f : NEGV;
    int len = lengths[bg];
    __syncthreads();
    float fcur = g_feats[0][bg][t];
    for (int s = 0; s < SEQ; s++) {
        float fnext = (s + 1 < SEQ) ? g_feats[s + 1][bg][t] : 0.f;
        float v[NTAG];
        float mx = -1e30f;
#pragma unroll
        for (int p = 0; p < NTAG; p++) {
            v[p] = alpha[b][p] + tr[t][p];
            mx = fmaxf(mx, v[p]);
        }
        float sum = 0.f;
#pragma unroll
        for (int p = 0; p < NTAG; p++) sum += __expf(v[p] - mx);
        float newv = mx + __logf(sum) + fcur;
        float keep = alpha[b][t];
        float nv = (s < len) ? newv : keep;
        __syncthreads();
        alpha[b][t] = nv;
        __syncthreads();
        fcur = fnext;
    }
    termS[b][t] = alpha[b][t] + tr[STOP_TAG][t];
    __syncthreads();
    if (t == 0) {
        float mx = -1e30f;
#pragma unroll
        for (int p = 0; p < NTAG; p++) mx = fmaxf(mx, termS[b][p]);
        float sum = 0.f;
#pragma unroll
        for (int p = 0; p < NTAG; p++) sum += __expf(termS[b][p] - mx);
        termS[b][0] = mx + __logf(sum);
    }
    __syncthreads();
    if (tid == 0) {
        float s2 = 0.f;
        for (int i = 0; i < 8; i++) s2 += termS[i][0];
        g_crf_part[blockIdx.x] = s2;
    }
}

__global__ void crf_finish(float* __restrict__ out) {
    float s = 0.f;
    for (int i = 0; i < 8; i++) s += g_crf_part[i];
    out[0] = s / (float)BATCH;
}

// ---------------- launch ----------------
extern "C" void kernel_launch(void* const* d_in, const int* in_sizes, int n_in,
                              void* d_out, int out_size) {
    const int*   tokens  = (const int*)  d_in[0];
    const int*   lengths = (const int*)  d_in[1];
    const float* W_emb   = (const float*)d_in[2];
    const float* W_ih_f  = (const float*)d_in[3];
    const float* W_hh_f  = (const float*)d_in[4];
    const float* b_f     = (const float*)d_in[5];
    const float* W_ih_b  = (const float*)d_in[6];
    const float* W_hh_b  = (const float*)d_in[7];
    const float* b_b     = (const float*)d_in[8];
    const float* h0      = (const float*)d_in[9];
    const float* c0      = (const float*)d_in[10];
    const float* W_out   = (const float*)d_in[11];
    const float* b_out   = (const float*)d_in[12];
    const float* trans   = (const float*)d_in[13];
    float* out = (float*)d_out;

    const int SMEM_LSTM = (16 * 513 * 2 + HID * BATCH) * 4;   // 196,736 B
    cudaFuncSetAttribute(lstm_persistent,
                         cudaFuncAttributeMaxDynamicSharedMemorySize, SMEM_LSTM);

    prep_kernel<<<1024, 256>>>(W_ih_f, W_ih_b, h0, W_out);
    xw_gemm<<<dim3(GATES / 128, SEQ, 2), 256>>>(tokens, W_emb, b_f, b_b);
    lstm_persistent<<<128, 256, SMEM_LSTM>>>(W_hh_f, W_hh_b, c0);
    feats_kernel<<<SEQ, 256>>>(b_out);
    crf_kernel<<<8, 96>>>(lengths, trans);
    crf_finish<<<1, 1>>>(out);
}

// round 13
// speedup vs baseline: 1.0239x; 1.0239x over previous
#include <cuda_runtime.h>
#include <math.h>

#define SEQ   512
#define BATCH 64
#define EMB   300
#define HID   512
#define GATES 2048   // 4*HID
#define NTAG  12
#define NEGV  (-10000.0f)
#define START_TAG 10
#define STOP_TAG  11
#define PREFIX_S 64

// ---------------- scratch (device globals; no allocation) ----------------
__device__ float g_xw[2][SEQ][GATES][BATCH];   // pre-activations x@W_ih.T+b
__device__ __align__(256) float g_hf[SEQ][HID][BATCH];   // forward hidden states
__device__ __align__(256) float g_hb[SEQ][HID][BATCH];   // backward hidden (scan order)
__device__ __align__(256) float g_hinit[2][HID][BATCH];  // transposed h0
__device__ float g_Wt_ih[2][EMB][GATES];       // W_ih transposed [e][j]
__device__ float g_Wout_t[2 * HID][NTAG];      // W_out transposed [k][t]
__device__ float g_feats[SEQ][BATCH][NTAG];
__device__ float g_crf_part[8];
__device__ unsigned g_cnt2[2];
__device__ unsigned g_gen2[2];
__device__ unsigned g_xwflag[2][SEQ];          // per-(dir,s) xw ready flags

// ---------------- f32x2 helpers ----------------
__device__ __forceinline__ unsigned long long splat2(float x) {
    unsigned long long r; unsigned u = __float_as_uint(x);
    asm("mov.b64 %0, {%1, %1};" : "=l"(r) : "r"(u));
    return r;
}
__device__ __forceinline__ void ffma2(unsigned long long& d,
                                      unsigned long long a,
                                      unsigned long long b) {
    asm("fma.rn.f32x2 %0, %1, %2, %0;" : "+l"(d) : "l"(a), "l"(b));
}
__device__ __forceinline__ unsigned long long addf2(unsigned long long a,
                                                    unsigned long long b) {
    unsigned long long r;
    asm("add.rn.f32x2 %0, %1, %2;" : "=l"(r) : "l"(a), "l"(b));
    return r;
}
__device__ __forceinline__ float2 unpack2(unsigned long long v) {
    unsigned lo, hi;
    asm("mov.b64 {%0, %1}, %2;" : "=r"(lo), "=r"(hi) : "l"(v));
    float2 f; f.x = __uint_as_float(lo); f.y = __uint_as_float(hi);
    return f;
}
__device__ __forceinline__ float sigf(float x) { return 1.f / (1.f + __expf(-x)); }
__device__ __forceinline__ float tanhfast(float x) { return 2.f / (1.f + __expf(-2.f * x)) - 1.f; }

__device__ __forceinline__ unsigned ld_acq(const unsigned* p) {
    unsigned v;
    asm volatile("ld.acquire.gpu.global.u32 %0, [%1];" : "=r"(v) : "l"(p) : "memory");
    return v;
}

#define CBAR() asm volatile("bar.sync 0, 512;" ::: "memory")
#define PBAR() asm volatile("bar.sync 1, 128;" ::: "memory")

// ---------------- prep: transposes + state init + flag/barrier reset ----------
__global__ void prep_kernel(const float* Wif, const float* Wib, const float* h0,
                            const float* Wout) {
    if (blockIdx.x == 0) {
        if (threadIdx.x < 2) {
            g_cnt2[threadIdx.x] = 0;
            g_gen2[threadIdx.x] = 0;
        }
        for (int l = threadIdx.x; l < 2 * SEQ; l += blockDim.x)
            ((unsigned*)g_xwflag)[l] = 0;
    }
    const int N_IH = 2 * EMB * GATES;
    const int N_H  = 2 * HID * BATCH;
    const int N_WO = NTAG * 2 * HID;
    const int total = N_IH + N_H + N_WO;
    for (int idx = blockIdx.x * blockDim.x + threadIdx.x; idx < total;
         idx += gridDim.x * blockDim.x) {
        int i = idx;
        if (i < N_IH) {
            int d = i / (EMB * GATES);
            int r = i % (EMB * GATES);
            int e = r / GATES, j = r % GATES;
            const float* W = d ? Wib : Wif;
            g_Wt_ih[d][e][j] = W[j * EMB + e];
        } else if ((i -= N_IH) < N_H) {
            int d = i / (HID * BATCH);
            int r = i % (HID * BATCH);
            int u = r / BATCH, b = r % BATCH;
            g_hinit[d][u][b] = h0[(d * BATCH + b) * HID + u];
        } else {
            i -= N_H;
            int k = i / NTAG, t = i % NTAG;
            g_Wout_t[k][t] = Wout[t * (2 * HID) + k];
        }
    }
}

// ---------------- input GEMM prefix (s < PREFIX_S only) ----------------
__global__ __launch_bounds__(256)
void xw_gemm(const int* __restrict__ tokens,
             const float* __restrict__ W_emb,
             const float* __restrict__ b_f,
             const float* __restrict__ b_b) {
    int dir = blockIdx.z;
    int s   = blockIdx.y;
    int n0  = blockIdx.x * 128;
    __shared__ float As[16][64];
    __shared__ float Bs[16][128];
    __shared__ int   tokS[64];
    int tid = threadIdx.x;
    if (tid < 64) {
        int srow = dir ? (SEQ - 1 - s) : s;
        tokS[tid] = tokens[tid * SEQ + srow];
    }
    __syncthreads();
    int c0 = (tid >> 3) * 4;
    int b0 = (tid & 7) * 8;
    unsigned long long acc[4][4] = {};
    for (int k0 = 0; k0 < 304; k0 += 16) {
        {
            int b = tid & 63, kk4 = (tid >> 6) * 4;
            int k = k0 + kk4;
            float4 v = {0.f, 0.f, 0.f, 0.f};
            if (k + 3 < EMB)
                v = *(const float4*)(W_emb + (size_t)tokS[b] * EMB + k);
            As[kk4 + 0][b] = v.x;
            As[kk4 + 1][b] = v.y;
            As[kk4 + 2][b] = v.z;
            As[kk4 + 3][b] = v.w;
        }
#pragma unroll
        for (int r = 0; r < 2; r++) {
            int idx = tid + 256 * r;
            int kk = idx >> 5, cg = idx & 31;
            float4 w = {0.f, 0.f, 0.f, 0.f};
            if (k0 + kk < EMB)
                w = *(const float4*)&g_Wt_ih[dir][k0 + kk][n0 + cg * 4];
            *(float4*)&Bs[kk][cg * 4] = w;
        }
        __syncthreads();
#pragma unroll
        for (int kk = 0; kk < 16; kk++) {
            float4 wv = *(const float4*)&Bs[kk][c0];
            unsigned long long w0 = splat2(wv.x), w1 = splat2(wv.y);
            unsigned long long w2 = splat2(wv.z), w3 = splat2(wv.w);
            ulonglong2 xA = *(const ulonglong2*)&As[kk][b0];
            ulonglong2 xB = *(const ulonglong2*)&As[kk][b0 + 4];
            ffma2(acc[0][0], xA.x, w0); ffma2(acc[0][1], xA.y, w0);
            ffma2(acc[0][2], xB.x, w0); ffma2(acc[0][3], xB.y, w0);
            ffma2(acc[1][0], xA.x, w1); ffma2(acc[1][1], xA.y, w1);
            ffma2(acc[1][2], xB.x, w1); ffma2(acc[1][3], xB.y, w1);
            ffma2(acc[2][0], xA.x, w2); ffma2(acc[2][1], xA.y, w2);
            ffma2(acc[2][2], xB.x, w2); ffma2(acc[2][3], xB.y, w2);
            ffma2(acc[3][0], xA.x, w3); ffma2(acc[3][1], xA.y, w3);
            ffma2(acc[3][2], xB.x, w3); ffma2(acc[3][3], xB.y, w3);
        }
        __syncthreads();
    }
    const float* bias = dir ? b_b : b_f;
#pragma unroll
    for (int cc = 0; cc < 4; cc++) {
        int j = n0 + c0 + cc;
        float bv = bias[j];
        float2 p0 = unpack2(acc[cc][0]), p1 = unpack2(acc[cc][1]);
        float2 p2 = unpack2(acc[cc][2]), p3 = unpack2(acc[cc][3]);
        float4 o0 = {p0.x + bv, p0.y + bv, p1.x + bv, p1.y + bv};
        float4 o1 = {p2.x + bv, p2.y + bv, p3.x + bv, p3.y + bv};
        *(float4*)&g_xw[dir][s][j][b0] = o0;
        *(float4*)&g_xw[dir][s][j][b0 + 4] = o1;
    }
}

// ---------------- fused persistent BiLSTM + in-kernel xw producer -------------
// 128 blocks x 640 thr. Threads [0,128) = producer warps (lowest wid -> lowest
// arbiter priority): compute xw tiles for s>=PREFIX_S, publish flags.
// Threads [128,640) = R10 consumer: 8 units x 4 gates x 64 batch, 2-way K-split.
#define SWS 513
#define SW_F   (16 * SWS * 2)          // 16416 floats
#define SH_F   (HID * BATCH)           // 32768 floats
#define PRO_F  (SW_F + SH_F)           // producer region base
__global__ __launch_bounds__(640, 1)
void lstm_fused(const int* __restrict__ tokens,
                const float* __restrict__ W_emb,
                const float* __restrict__ b_f,
                const float* __restrict__ b_b,
                const float* __restrict__ Whf, const float* __restrict__ Whb,
                const float* __restrict__ c0in) {
    extern __shared__ float smem[];
    float2* sW = (float2*)smem;               // [16 cp][SWS] float2
    float*  sH = smem + SW_F;                 // full h: 512 k x 64 b
    float*  As = smem + PRO_F;                // producer [16][64]
    float*  Bs = As + 1024;                   // producer [16][64]
    int*    tokS = (int*)(Bs + 1024);         // producer [64]

    int tid = threadIdx.x;
    int bid = blockIdx.x;
    int dir = bid >> 6;
    int u0  = (bid & 63) * 8;
    const float* Whh = dir ? Whb : Whf;

    // prologue (all 640 threads): stage W pairs for the consumer
    for (int l = tid; l < 16 * 512; l += 640) {
        int cp = l >> 9, k = l & 511;
        int ca = cp * 2, cb = ca + 1;
        int ja = (ca >> 3) * HID + u0 + (ca & 7);
        int jb = (cb >> 3) * HID + u0 + (cb & 7);
        float2 v;
        v.x = Whh[ja * HID + k];
        v.y = Whh[jb * HID + k];
        sW[cp * SWS + k] = v;
    }
    __syncthreads();

    if (tid < 128) {
        // ================= PRODUCER =================
        int pt = tid;
        int c0 = (pt >> 3) * 4;          // 0..60
        int b0p = (pt & 7) * 8;
#pragma unroll 1
        for (int j = 0; j < 7; j++) {
            int p2 = bid + 128 * j;
            int s2 = PREFIX_S + (p2 >> 1);
            int d2 = p2 & 1;
            if (pt < 64) {
                int srow = d2 ? (SEQ - 1 - s2) : s2;
                tokS[pt] = tokens[pt * SEQ + srow];
            }
            PBAR();
            const float* bias = d2 ? b_b : b_f;
#pragma unroll 1
            for (int ch = 0; ch < 32; ch++) {
                int n0 = ch * 64;
                unsigned long long acc[4][4] = {};
                for (int k0 = 0; k0 < 304; k0 += 16) {
                    {
                        int b = pt & 63, half = pt >> 6;
#pragma unroll
                        for (int q = 0; q < 2; q++) {
                            int kk = half * 8 + q * 4;
                            int k = k0 + kk;
                            float4 v = {0.f, 0.f, 0.f, 0.f};
                            if (k + 3 < EMB)
                                v = *(const float4*)(W_emb + (size_t)tokS[b] * EMB + k);
                            As[(kk + 0) * 64 + b] = v.x;
                            As[(kk + 1) * 64 + b] = v.y;
                            As[(kk + 2) * 64 + b] = v.z;
                            As[(kk + 3) * 64 + b] = v.w;
                        }
                    }
#pragma unroll
                    for (int r = 0; r < 2; r++) {
                        int idx = pt + 128 * r;
                        int kk = idx >> 4, cg = idx & 15;
                        float4 w = {0.f, 0.f, 0.f, 0.f};
                        if (k0 + kk < EMB)
                            w = *(const float4*)&g_Wt_ih[d2][k0 + kk][n0 + cg * 4];
                        *(float4*)&Bs[kk * 64 + cg * 4] = w;
                    }
                    PBAR();
#pragma unroll
                    for (int kk = 0; kk < 16; kk++) {
                        float4 wv = *(const float4*)&Bs[kk * 64 + c0];
                        unsigned long long w0 = splat2(wv.x), w1 = splat2(wv.y);
                        unsigned long long w2 = splat2(wv.z), w3 = splat2(wv.w);
                        ulonglong2 xA = *(const ulonglong2*)&As[kk * 64 + b0p];
                        ulonglong2 xB = *(const ulonglong2*)&As[kk * 64 + b0p + 4];
                        ffma2(acc[0][0], xA.x, w0); ffma2(acc[0][1], xA.y, w0);
                        ffma2(acc[0][2], xB.x, w0); ffma2(acc[0][3], xB.y, w0);
                        ffma2(acc[1][0], xA.x, w1); ffma2(acc[1][1], xA.y, w1);
                        ffma2(acc[1][2], xB.x, w1); ffma2(acc[1][3], xB.y, w1);
                        ffma2(acc[2][0], xA.x, w2); ffma2(acc[2][1], xA.y, w2);
                        ffma2(acc[2][2], xB.x, w2); ffma2(acc[2][3], xB.y, w2);
                        ffma2(acc[3][0], xA.x, w3); ffma2(acc[3][1], xA.y, w3);
                        ffma2(acc[3][2], xB.x, w3); ffma2(acc[3][3], xB.y, w3);
                    }
                    PBAR();
                }
#pragma unroll
                for (int cc = 0; cc < 4; cc++) {
                    int jc = n0 + c0 + cc;
                    float bv = bias[jc];
                    float2 p0 = unpack2(acc[cc][0]), p1 = unpack2(acc[cc][1]);
                    float2 p2_ = unpack2(acc[cc][2]), p3 = unpack2(acc[cc][3]);
                    float4 o0 = {p0.x + bv, p0.y + bv, p1.x + bv, p1.y + bv};
                    float4 o1 = {p2_.x + bv, p2_.y + bv, p3.x + bv, p3.y + bv};
                    *(float4*)&g_xw[d2][s2][jc][b0p] = o0;
                    *(float4*)&g_xw[d2][s2][jc][b0p + 4] = o1;
                }
            }
            PBAR();
            if (pt == 0) {
                asm volatile("fence.acq_rel.gpu;" ::: "memory");
                asm volatile("st.relaxed.gpu.global.u32 [%0], %1;"
                             :: "l"(&g_xwflag[d2][s2]), "r"(1u) : "memory");
            }
        }
        return;
    }

    // ================= CONSUMER (R10 structure) =================
    int ctid = tid - 128;
    int kg  = ctid >> 8;                         // 0 or 1 (k-half)
    int lo  = ctid & 255;
    int cp  = (lo >> 3) & 15;                    // col-pair 0..15
    int c0i = cp * 2;
    int b0  = (lo & 7) * 4 + ((lo >> 7) & 1) * 32;  // batch base, 4 per thread

    float cst;                                   // 1 cell elem per thread
    {
        int uu = (ctid >> 6) & 7, b = ctid & 63;
        cst = c0in[(dir * BATCH + b) * HID + (u0 + uu)];
    }

    const float2* wrow = sW + cp * SWS;
    int j0 = (c0i >> 3) * HID + u0 + (c0i & 7);
    int c1i = c0i + 1;
    int j1 = (c1i >> 3) * HID + u0 + (c1i & 7);
    int k0 = kg * 256;

    for (int s = 0; s < SEQ; s++) {
        const float* hprev = (s == 0) ? &g_hinit[dir][0][0]
                                      : (dir ? &g_hb[s - 1][0][0] : &g_hf[s - 1][0][0]);
        // wait for this step's xw (normally already produced far ahead)
        if (ctid == 0 && s >= PREFIX_S) {
            unsigned v;
            do { v = ld_acq(&g_xwflag[dir][s]); } while (!v);
        }
        CBAR();

        // stage whole h: 32768 floats = 8192 f4; 16 f4/thread
#pragma unroll
        for (int r = 0; r < 16; r++) {
            int m = ctid + 512 * r;
            float4 v = *(const float4*)(hprev + m * 4);
            *(float4*)(sH + m * 4) = v;
        }
        // hoist xw loads for reducer group
        float4 x0, x1;
        if (kg == 0) {
            x0 = *(const float4*)&g_xw[dir][s][j0][b0];
            x1 = *(const float4*)&g_xw[dir][s][j1][b0];
        }
        CBAR();

        // compute this k-half: 128 iterations of 2 k
        unsigned long long a00 = 0, a01 = 0, a10 = 0, a11 = 0;
#pragma unroll 8
        for (int kk = k0; kk < k0 + 256; kk += 2) {
            float2 wA = wrow[kk];
            float2 wB = wrow[kk + 1];
            unsigned long long hA0 = *(const unsigned long long*)(sH + kk * BATCH + b0);
            unsigned long long hA1 = *(const unsigned long long*)(sH + kk * BATCH + b0 + 2);
            unsigned long long hB0 = *(const unsigned long long*)(sH + (kk + 1) * BATCH + b0);
            unsigned long long hB1 = *(const unsigned long long*)(sH + (kk + 1) * BATCH + b0 + 2);
            unsigned long long wa0 = splat2(wA.x), wa1 = splat2(wA.y);
            unsigned long long wb0 = splat2(wB.x), wb1 = splat2(wB.y);
            ffma2(a00, hA0, wa0); ffma2(a01, hA1, wa0);
            ffma2(a10, hA0, wa1); ffma2(a11, hA1, wa1);
            ffma2(a00, hB0, wb0); ffma2(a01, hB1, wb0);
            ffma2(a10, hB0, wb1); ffma2(a11, hB1, wb1);
        }
        CBAR();   // everyone done reading sH

        // K-split reduce: kg1 parks 4 u64 at slot lo
        if (kg == 1) {
            ulonglong2* pp = (ulonglong2*)((unsigned long long*)sH + (size_t)lo * 4);
            pp[0] = make_ulonglong2(a00, a01);
            pp[1] = make_ulonglong2(a10, a11);
        }
        CBAR();

        float* sG = sH + 2048;                   // gates region (beyond 8KB park)
        if (kg == 0) {
            const ulonglong2* pp = (const ulonglong2*)((unsigned long long*)sH + (size_t)lo * 4);
            ulonglong2 v0 = pp[0], v1 = pp[1];
            a00 = addf2(a00, v0.x); a01 = addf2(a01, v0.y);
            a10 = addf2(a10, v1.x); a11 = addf2(a11, v1.y);
            float2 p0 = unpack2(a00), p1 = unpack2(a01);
            float2 q0 = unpack2(a10), q1 = unpack2(a11);
            float4 o0 = {p0.x + x0.x, p0.y + x0.y, p1.x + x0.z, p1.y + x0.w};
            float4 o1 = {q0.x + x1.x, q0.y + x1.y, q1.x + x1.z, q1.y + x1.w};
            *(float4*)(sG + c0i * 68 + b0) = o0;
            *(float4*)(sG + c1i * 68 + b0) = o1;
        }
        CBAR();

        // pointwise: 1 elem/thread; c in registers
        float* hout = dir ? &g_hb[s][0][0] : &g_hf[s][0][0];
        {
            int uu = (ctid >> 6) & 7, b = ctid & 63;
            float gi = sG[uu * 68 + b];
            float gf = sG[(8 + uu) * 68 + b];
            float gg = sG[(16 + uu) * 68 + b];
            float go = sG[(24 + uu) * 68 + b];
            float iv = sigf(gi), fv = sigf(gf), ov = sigf(go);
            float c = fv * cst + iv * tanhfast(gg);
            cst = c;
            hout[(u0 + uu) * BATCH + b] = ov * tanhfast(c);
        }
        CBAR();

        // per-direction grid barrier, skipped after last step
        if (s < SEQ - 1) {
            if (ctid == 0) {
                unsigned target = (unsigned)(s + 1);
                unsigned prev;
                asm volatile("atom.acq_rel.gpu.global.add.u32 %0, [%1], 1;"
                             : "=r"(prev) : "l"(&g_cnt2[dir]) : "memory");
                if (prev == 63) {
                    asm volatile("st.relaxed.gpu.global.u32 [%0], %1;"
                                 :: "l"(&g_cnt2[dir]), "r"(0u) : "memory");
                    asm volatile("st.release.gpu.global.u32 [%0], %1;"
                                 :: "l"(&g_gen2[dir]), "r"(target) : "memory");
                } else {
                    unsigned g;
                    do { g = ld_acq(&g_gen2[dir]); } while (g < target);
                }
            }
            CBAR();
        }
    }
}

// ---------------- feats: K-split, 12 independent chains per thread ----------------
__global__ __launch_bounds__(256)
void feats_kernel(const float* __restrict__ b_out) {
    int s = blockIdx.x;
    int tid = threadIdx.x;
    int b = tid & 63;
    int slice = tid >> 6;
    __shared__ float sred[256][NTAG];
    float a[NTAG];
#pragma unroll
    for (int t = 0; t < NTAG; t++) a[t] = 0.f;

    int base = slice * 256;
    const float* hbase = (base < HID) ? &g_hf[s][base][0]
                                      : &g_hb[SEQ - 1 - s][base - HID][0];
#pragma unroll 4
    for (int k = 0; k < 256; k++) {
        float h = hbase[k * BATCH + b];
        int kg = base + k;
        float4 w0 = *(const float4*)&g_Wout_t[kg][0];
        float4 w1 = *(const float4*)&g_Wout_t[kg][4];
        float4 w2 = *(const float4*)&g_Wout_t[kg][8];
        a[0] += h * w0.x;  a[1] += h * w0.y;  a[2]  += h * w0.z;  a[3]  += h * w0.w;
        a[4] += h * w1.x;  a[5] += h * w1.y;  a[6]  += h * w1.z;  a[7]  += h * w1.w;
        a[8] += h * w2.x;  a[9] += h * w2.y;  a[10] += h * w2.z;  a[11] += h * w2.w;
    }
#pragma unroll
    for (int t = 0; t < NTAG; t++) sred[tid][t] = a[t];
    __syncthreads();
    if (tid < 64) {
#pragma unroll
        for (int t = 0; t < NTAG; t++) {
            float v = b_out[t] + sred[tid][t] + sred[64 + tid][t]
                    + sred[128 + tid][t] + sred[192 + tid][t];
            g_feats[s][tid][t] = v;
        }
    }
}

// ---------------- CRF forward: 8 blocks x 8 batches, feats prefetch ----------------
__global__ __launch_bounds__(96)
void crf_kernel(const int* __restrict__ lengths,
                const float* __restrict__ trans) {
    __shared__ float alpha[8][NTAG];
    __shared__ float tr[NTAG][NTAG];
    __shared__ float termS[8][NTAG];
    int tid = threadIdx.x;
    int b = tid / NTAG, t = tid % NTAG;
    int bg = blockIdx.x * 8 + b;
    for (int l = tid; l < NTAG * NTAG; l += 96)
        tr[l / NTAG][l % NTAG] = trans[l];
    alpha[b][t] = (t == START_TAG) ? 0.f : NEGV;
    int len = lengths[bg];
    __syncthreads();
    float fcur = g_feats[0][bg][t];
    for (int s = 0; s < SEQ; s++) {
        float fnext = (s + 1 < SEQ) ? g_feats[s + 1][bg][t] : 0.f;
        float v[NTAG];
        float mx = -1e30f;
#pragma unroll
        for (int p = 0; p < NTAG; p++) {
            v[p] = alpha[b][p] + tr[t][p];
            mx = fmaxf(mx, v[p]);
        }
        float sum = 0.f;
#pragma unroll
        for (int p = 0; p < NTAG; p++) sum += __expf(v[p] - mx);
        float newv = mx + __logf(sum) + fcur;
        float keep = alpha[b][t];
        float nv = (s < len) ? newv : keep;
        __syncthreads();
        alpha[b][t] = nv;
        __syncthreads();
        fcur = fnext;
    }
    termS[b][t] = alpha[b][t] + tr[STOP_TAG][t];
    __syncthreads();
    if (t == 0) {
        float mx = -1e30f;
#pragma unroll
        for (int p = 0; p < NTAG; p++) mx = fmaxf(mx, termS[b][p]);
        float sum = 0.f;
#pragma unroll
        for (int p = 0; p < NTAG; p++) sum += __expf(termS[b][p] - mx);
        termS[b][0] = mx + __logf(sum);
    }
    __syncthreads();
    if (tid == 0) {
        float s2 = 0.f;
        for (int i = 0; i < 8; i++) s2 += termS[i][0];
        g_crf_part[blockIdx.x] = s2;
    }
}

__global__ void crf_finish(float* __restrict__ out) {
    float s = 0.f;
    for (int i = 0; i < 8; i++) s += g_crf_part[i];
    out[0] = s / (float)BATCH;
}

// ---------------- launch ----------------
extern "C" void kernel_launch(void* const* d_in, const int* in_sizes, int n_in,
                              void* d_out, int out_size) {
    const int*   tokens  = (const int*)  d_in[0];
    const int*   lengths = (const int*)  d_in[1];
    const float* W_emb   = (const float*)d_in[2];
    const float* W_ih_f  = (const float*)d_in[3];
    const float* W_hh_f  = (const float*)d_in[4];
    const float* b_f     = (const float*)d_in[5];
    const float* W_ih_b  = (const float*)d_in[6];
    const float* W_hh_b  = (const float*)d_in[7];
    const float* b_b     = (const float*)d_in[8];
    const float* h0      = (const float*)d_in[9];
    const float* c0      = (const float*)d_in[10];
    const float* W_out   = (const float*)d_in[11];
    const float* b_out   = (const float*)d_in[12];
    const float* trans   = (const float*)d_in[13];
    float* out = (float*)d_out;

    const int SMEM_LSTM = (PRO_F + 1024 + 1024 + 64) * 4;   // 205,184 B
    cudaFuncSetAttribute(lstm_fused,
                         cudaFuncAttributeMaxDynamicSharedMemorySize, SMEM_LSTM);

    prep_kernel<<<1024, 256>>>(W_ih_f, W_ih_b, h0, W_out);
    xw_gemm<<<dim3(GATES / 128, PREFIX_S, 2), 256>>>(tokens, W_emb, b_f, b_b);
    lstm_fused<<<128, 640, SMEM_LSTM>>>(tokens, W_emb, b_f, b_b,
                                        W_hh_f, W_hh_b, c0);
    feats_kernel<<<SEQ, 256>>>(b_out);
    crf_kernel<<<8, 96>>>(lengths, trans);
    crf_finish<<<1, 1>>>(out);
}

// round 14
// speedup vs baseline: 1.1945x; 1.1666x over previous
#include <cuda_runtime.h>
#include <math.h>

#define SEQ   512
#define BATCH 64
#define EMB   300
#define HID   512
#define GATES 2048   // 4*HID
#define NTAG  12
#define NEGV  (-10000.0f)
#define START_TAG 10
#define STOP_TAG  11

// ---------------- scratch (device globals; no allocation) ----------------
__device__ float g_xw[2][SEQ][GATES][BATCH];   // pre-activations x@W_ih.T+b
__device__ __align__(256) float g_hf[SEQ][HID][BATCH];   // forward hidden states
__device__ __align__(256) float g_hb[SEQ][HID][BATCH];   // backward hidden (scan order)
__device__ __align__(256) float g_hinit[2][HID][BATCH];  // transposed h0
__device__ float g_Wt_ih[2][EMB][GATES];       // W_ih transposed [e][j]
__device__ float g_Wout_t[2 * HID][NTAG];      // W_out transposed [k][t]
__device__ float g_feats[SEQ][BATCH][NTAG];
__device__ float g_crf_part[8];
__device__ unsigned g_cnt4[4];                 // per (dir,bgroup) chain counters
__device__ unsigned g_gen4[4];

// ---------------- f32x2 helpers ----------------
__device__ __forceinline__ unsigned long long splat2(float x) {
    unsigned long long r; unsigned u = __float_as_uint(x);
    asm("mov.b64 %0, {%1, %1};" : "=l"(r) : "r"(u));
    return r;
}
__device__ __forceinline__ void ffma2(unsigned long long& d,
                                      unsigned long long a,
                                      unsigned long long b) {
    asm("fma.rn.f32x2 %0, %1, %2, %0;" : "+l"(d) : "l"(a), "l"(b));
}
__device__ __forceinline__ unsigned long long addf2(unsigned long long a,
                                                    unsigned long long b) {
    unsigned long long r;
    asm("add.rn.f32x2 %0, %1, %2;" : "=l"(r) : "l"(a), "l"(b));
    return r;
}
__device__ __forceinline__ float2 unpack2(unsigned long long v) {
    unsigned lo, hi;
    asm("mov.b64 {%0, %1}, %2;" : "=r"(lo), "=r"(hi) : "l"(v));
    float2 f; f.x = __uint_as_float(lo); f.y = __uint_as_float(hi);
    return f;
}
__device__ __forceinline__ float sigf(float x) { return 1.f / (1.f + __expf(-x)); }
__device__ __forceinline__ float tanhfast(float x) { return 2.f / (1.f + __expf(-2.f * x)) - 1.f; }

__device__ __forceinline__ unsigned ld_acq(const unsigned* p) {
    unsigned v;
    asm volatile("ld.acquire.gpu.global.u32 %0, [%1];" : "=r"(v) : "l"(p) : "memory");
    return v;
}

// ---------------- prep: transposes + state init + barrier reset ----------------
__global__ void prep_kernel(const float* Wif, const float* Wib, const float* h0,
                            const float* Wout) {
    if (blockIdx.x == 0 && threadIdx.x < 4) {
        g_cnt4[threadIdx.x] = 0;
        g_gen4[threadIdx.x] = 0;
    }
    const int N_IH = 2 * EMB * GATES;
    const int N_H  = 2 * HID * BATCH;
    const int N_WO = NTAG * 2 * HID;
    const int total = N_IH + N_H + N_WO;
    for (int idx = blockIdx.x * blockDim.x + threadIdx.x; idx < total;
         idx += gridDim.x * blockDim.x) {
        int i = idx;
        if (i < N_IH) {
            int d = i / (EMB * GATES);
            int r = i % (EMB * GATES);
            int e = r / GATES, j = r % GATES;
            const float* W = d ? Wib : Wif;
            g_Wt_ih[d][e][j] = W[j * EMB + e];
        } else if ((i -= N_IH) < N_H) {
            int d = i / (HID * BATCH);
            int r = i % (HID * BATCH);
            int u = r / BATCH, b = r % BATCH;
            g_hinit[d][u][b] = h0[(d * BATCH + b) * HID + u];
        } else {
            i -= N_H;
            int k = i / NTAG, t = i % NTAG;
            g_Wout_t[k][t] = Wout[t * (2 * HID) + k];
        }
    }
}

// ---------------- input GEMM (f32x2) ----------------
__global__ __launch_bounds__(256)
void xw_gemm(const int* __restrict__ tokens,
             const float* __restrict__ W_emb,
             const float* __restrict__ b_f,
             const float* __restrict__ b_b) {
    int dir = blockIdx.z;
    int s   = blockIdx.y;
    int n0  = blockIdx.x * 128;
    __shared__ float As[16][64];
    __shared__ float Bs[16][128];
    __shared__ int   tokS[64];
    int tid = threadIdx.x;
    if (tid < 64) {
        int srow = dir ? (SEQ - 1 - s) : s;
        tokS[tid] = tokens[tid * SEQ + srow];
    }
    __syncthreads();
    int c0 = (tid >> 3) * 4;
    int b0 = (tid & 7) * 8;
    unsigned long long acc[4][4] = {};
    for (int k0 = 0; k0 < 304; k0 += 16) {
        {
            int b = tid & 63, kk4 = (tid >> 6) * 4;
            int k = k0 + kk4;
            float4 v = {0.f, 0.f, 0.f, 0.f};
            if (k + 3 < EMB)
                v = *(const float4*)(W_emb + (size_t)tokS[b] * EMB + k);
            As[kk4 + 0][b] = v.x;
            As[kk4 + 1][b] = v.y;
            As[kk4 + 2][b] = v.z;
            As[kk4 + 3][b] = v.w;
        }
#pragma unroll
        for (int r = 0; r < 2; r++) {
            int idx = tid + 256 * r;
            int kk = idx >> 5, cg = idx & 31;
            float4 w = {0.f, 0.f, 0.f, 0.f};
            if (k0 + kk < EMB)
                w = *(const float4*)&g_Wt_ih[dir][k0 + kk][n0 + cg * 4];
            *(float4*)&Bs[kk][cg * 4] = w;
        }
        __syncthreads();
#pragma unroll
        for (int kk = 0; kk < 16; kk++) {
            float4 wv = *(const float4*)&Bs[kk][c0];
            unsigned long long w0 = splat2(wv.x), w1 = splat2(wv.y);
            unsigned long long w2 = splat2(wv.z), w3 = splat2(wv.w);
            ulonglong2 xA = *(const ulonglong2*)&As[kk][b0];
            ulonglong2 xB = *(const ulonglong2*)&As[kk][b0 + 4];
            ffma2(acc[0][0], xA.x, w0); ffma2(acc[0][1], xA.y, w0);
            ffma2(acc[0][2], xB.x, w0); ffma2(acc[0][3], xB.y, w0);
            ffma2(acc[1][0], xA.x, w1); ffma2(acc[1][1], xA.y, w1);
            ffma2(acc[1][2], xB.x, w1); ffma2(acc[1][3], xB.y, w1);
            ffma2(acc[2][0], xA.x, w2); ffma2(acc[2][1], xA.y, w2);
            ffma2(acc[2][2], xB.x, w2); ffma2(acc[2][3], xB.y, w2);
            ffma2(acc[3][0], xA.x, w3); ffma2(acc[3][1], xA.y, w3);
            ffma2(acc[3][2], xB.x, w3); ffma2(acc[3][3], xB.y, w3);
        }
        __syncthreads();
    }
    const float* bias = dir ? b_b : b_f;
#pragma unroll
    for (int cc = 0; cc < 4; cc++) {
        int j = n0 + c0 + cc;
        float bv = bias[j];
        float2 p0 = unpack2(acc[cc][0]), p1 = unpack2(acc[cc][1]);
        float2 p2 = unpack2(acc[cc][2]), p3 = unpack2(acc[cc][3]);
        float4 o0 = {p0.x + bv, p0.y + bv, p1.x + bv, p1.y + bv};
        float4 o1 = {p2.x + bv, p2.y + bv, p3.x + bv, p3.y + bv};
        *(float4*)&g_xw[dir][s][j][b0] = o0;
        *(float4*)&g_xw[dir][s][j][b0 + 4] = o1;
    }
}

// ---------------- persistent fused BiLSTM: 4 independent (dir,bgroup) chains ----
// 128 blocks x 512 thr. Block = (dir, bgroup of 32 batch, 16 units = 64 cols).
// Thread = (kg 0/1, cp 0..31, bq 0..7): 2 cols x 4 batch x 256 k.
// Chains sync independently: 32 arrivals each, decoupled spread.
#define SWS 513
__global__ __launch_bounds__(512, 1)
void lstm_persistent(const float* __restrict__ Whf, const float* __restrict__ Whb,
                     const float* __restrict__ c0in) {
    extern __shared__ float smem[];
    float2* sW = (float2*)smem;               // [32 cp][SWS] float2 = 131,328 B
    float*  sH = smem + 32 * SWS * 2;         // h slab: 512 k x 32 b = 65,536 B

    int tid = threadIdx.x;
    int bid = blockIdx.x;
    int dir = bid >> 6;
    int bg  = (bid >> 5) & 1;                 // batch group 0/1 (32 batch each)
    int u0  = (bid & 31) * 16;                // 16 hidden units
    int chain = dir * 2 + bg;
    const float* Whh = dir ? Whb : Whf;

    // stage W pairs: sW[cp][k] = (W[col 2cp][k], W[col 2cp+1][k])
    // col c (0..63): gate = c>>4, unit = c&15
    for (int l = tid; l < 32 * 512; l += 512) {
        int cp = l >> 9, k = l & 511;
        int ca = cp * 2, cb = ca + 1;
        int ja = (ca >> 4) * HID + u0 + (ca & 15);
        int jb = (cb >> 4) * HID + u0 + (cb & 15);
        float2 v;
        v.x = Whh[ja * HID + k];
        v.y = Whh[jb * HID + k];
        sW[cp * SWS + k] = v;
    }

    int kg  = tid >> 8;                          // k-half 0/1 (256 k each)
    int lo  = tid & 255;
    int cp  = lo >> 3;                           // col-pair 0..31
    int c0i = cp * 2, c1i = c0i + 1;
    int b0  = (lo & 7) * 4;                      // local batch base 0..28
    int gb0 = bg * 32 + b0;                      // global batch base
    int k0  = kg * 256;

    float cst;                                   // 1 cell elem per thread
    {
        int uu = (tid >> 5) & 15, b = tid & 31;
        cst = c0in[(dir * BATCH + bg * 32 + b) * HID + (u0 + uu)];
    }
    __syncthreads();

    const float2* wrow = sW + cp * SWS;
    int j0 = (c0i >> 4) * HID + u0 + (c0i & 15);
    int j1 = (c1i >> 4) * HID + u0 + (c1i & 15);

    for (int s = 0; s < SEQ; s++) {
        const float* hprev = (s == 0) ? &g_hinit[dir][0][0]
                                      : (dir ? &g_hb[s - 1][0][0] : &g_hf[s - 1][0][0]);
        // hoist xw loads for reducer group (kg==0)
        float4 x0, x1;
        if (kg == 0) {
            x0 = *(const float4*)&g_xw[dir][s][j0][gb0];
            x1 = *(const float4*)&g_xw[dir][s][j1][gb0];
        }

        // stage h slab: 512 k x 32 b = 16384 floats = 4096 f4; 8 f4/thread
#pragma unroll
        for (int r = 0; r < 8; r++) {
            int m = tid + 512 * r;                 // f4 idx 0..4095
            int k = m >> 3, c4 = m & 7;            // 8 f4 per k-row
            float4 v = *(const float4*)(hprev + k * BATCH + bg * 32 + c4 * 4);
            *(float4*)(sH + k * 32 + c4 * 4) = v;
        }
        __syncthreads();

        // compute this k-half: 128 iterations of 2 k
        unsigned long long a00 = 0, a01 = 0, a10 = 0, a11 = 0;
#pragma unroll 8
        for (int kk = k0; kk < k0 + 256; kk += 2) {
            float2 wA = wrow[kk];
            float2 wB = wrow[kk + 1];
            unsigned long long hA0 = *(const unsigned long long*)(sH + kk * 32 + b0);
            unsigned long long hA1 = *(const unsigned long long*)(sH + kk * 32 + b0 + 2);
            unsigned long long hB0 = *(const unsigned long long*)(sH + (kk + 1) * 32 + b0);
            unsigned long long hB1 = *(const unsigned long long*)(sH + (kk + 1) * 32 + b0 + 2);
            unsigned long long wa0 = splat2(wA.x), wa1 = splat2(wA.y);
            unsigned long long wb0 = splat2(wB.x), wb1 = splat2(wB.y);
            ffma2(a00, hA0, wa0); ffma2(a01, hA1, wa0);
            ffma2(a10, hA0, wa1); ffma2(a11, hA1, wa1);
            ffma2(a00, hB0, wb0); ffma2(a01, hB1, wb0);
            ffma2(a10, hB0, wb1); ffma2(a11, hB1, wb1);
        }
        __syncthreads();   // everyone done reading sH

        // K-split reduce: kg1 parks 4 u64 at slot lo (8KB, aliases sH head)
        if (kg == 1) {
            ulonglong2* pp = (ulonglong2*)((unsigned long long*)sH + (size_t)lo * 4);
            pp[0] = make_ulonglong2(a00, a01);
            pp[1] = make_ulonglong2(a10, a11);
        }
        __syncthreads();

        float* sG = sH + 2048;                   // gates: 64 cols x 36 (beyond park)
        if (kg == 0) {
            const ulonglong2* pp = (const ulonglong2*)((unsigned long long*)sH + (size_t)lo * 4);
            ulonglong2 v0 = pp[0], v1 = pp[1];
            a00 = addf2(a00, v0.x); a01 = addf2(a01, v0.y);
            a10 = addf2(a10, v1.x); a11 = addf2(a11, v1.y);
            float2 p0 = unpack2(a00), p1 = unpack2(a01);
            float2 q0 = unpack2(a10), q1 = unpack2(a11);
            float4 o0 = {p0.x + x0.x, p0.y + x0.y, p1.x + x0.z, p1.y + x0.w};
            float4 o1 = {q0.x + x1.x, q0.y + x1.y, q1.x + x1.z, q1.y + x1.w};
            *(float4*)(sG + c0i * 36 + b0) = o0;
            *(float4*)(sG + c1i * 36 + b0) = o1;
        }
        __syncthreads();

        // pointwise: 1 elem/thread (16 units x 32 batch); c in registers
        float* hout = dir ? &g_hb[s][0][0] : &g_hf[s][0][0];
        {
            int uu = (tid >> 5) & 15, b = tid & 31;
            float gi = sG[(0 + uu) * 36 + b];
            float gf = sG[(16 + uu) * 36 + b];
            float gg = sG[(32 + uu) * 36 + b];
            float go = sG[(48 + uu) * 36 + b];
            float iv = sigf(gi), fv = sigf(gf), ov = sigf(go);
            float c = fv * cst + iv * tanhfast(gg);
            cst = c;
            hout[(u0 + uu) * BATCH + bg * 32 + b] = ov * tanhfast(c);
        }
        __syncthreads();

        // per-chain grid barrier (32 arrivals), skipped after last step
        if (s < SEQ - 1) {
            if (tid == 0) {
                unsigned target = (unsigned)(s + 1);
                unsigned prev;
                asm volatile("atom.acq_rel.gpu.global.add.u32 %0, [%1], 1;"
                             : "=r"(prev) : "l"(&g_cnt4[chain]) : "memory");
                if (prev == 31) {
                    asm volatile("st.relaxed.gpu.global.u32 [%0], %1;"
                                 :: "l"(&g_cnt4[chain]), "r"(0u) : "memory");
                    asm volatile("st.release.gpu.global.u32 [%0], %1;"
                                 :: "l"(&g_gen4[chain]), "r"(target) : "memory");
                } else {
                    unsigned g;
                    do { g = ld_acq(&g_gen4[chain]); } while (g < target);
                }
            }
            __syncthreads();
        }
    }
}

// ---------------- feats: K-split, 12 independent chains per thread ----------------
__global__ __launch_bounds__(256)
void feats_kernel(const float* __restrict__ b_out) {
    int s = blockIdx.x;
    int tid = threadIdx.x;
    int b = tid & 63;
    int slice = tid >> 6;
    __shared__ float sred[256][NTAG];
    float a[NTAG];
#pragma unroll
    for (int t = 0; t < NTAG; t++) a[t] = 0.f;

    int base = slice * 256;
    const float* hbase = (base < HID) ? &g_hf[s][base][0]
                                      : &g_hb[SEQ - 1 - s][base - HID][0];
#pragma unroll 4
    for (int k = 0; k < 256; k++) {
        float h = hbase[k * BATCH + b];
        int kg = base + k;
        float4 w0 = *(const float4*)&g_Wout_t[kg][0];
        float4 w1 = *(const float4*)&g_Wout_t[kg][4];
        float4 w2 = *(const float4*)&g_Wout_t[kg][8];
        a[0] += h * w0.x;  a[1] += h * w0.y;  a[2]  += h * w0.z;  a[3]  += h * w0.w;
        a[4] += h * w1.x;  a[5] += h * w1.y;  a[6]  += h * w1.z;  a[7]  += h * w1.w;
        a[8] += h * w2.x;  a[9] += h * w2.y;  a[10] += h * w2.z;  a[11] += h * w2.w;
    }
#pragma unroll
    for (int t = 0; t < NTAG; t++) sred[tid][t] = a[t];
    __syncthreads();
    if (tid < 64) {
#pragma unroll
        for (int t = 0; t < NTAG; t++) {
            float v = b_out[t] + sred[tid][t] + sred[64 + tid][t]
                    + sred[128 + tid][t] + sred[192 + tid][t];
            g_feats[s][tid][t] = v;
        }
    }
}

// ---------------- CRF forward: 8 blocks x 8 batches, feats prefetch ----------------
__global__ __launch_bounds__(96)
void crf_kernel(const int* __restrict__ lengths,
                const float* __restrict__ trans) {
    __shared__ float alpha[8][NTAG];
    __shared__ float tr[NTAG][NTAG];
    __shared__ float termS[8][NTAG];
    int tid = threadIdx.x;
    int b = tid / NTAG, t = tid % NTAG;
    int bg = blockIdx.x * 8 + b;
    for (int l = tid; l < NTAG * NTAG; l += 96)
        tr[l / NTAG][l % NTAG] = trans[l];
    alpha[b][t] = (t == START_TAG) ? 0.f : NEGV;
    int len = lengths[bg];
    __syncthreads();
    float fcur = g_feats[0][bg][t];
    for (int s = 0; s < SEQ; s++) {
        float fnext = (s + 1 < SEQ) ? g_feats[s + 1][bg][t] : 0.f;
        float v[NTAG];
        float mx = -1e30f;
#pragma unroll
        for (int p = 0; p < NTAG; p++) {
            v[p] = alpha[b][p] + tr[t][p];
            mx = fmaxf(mx, v[p]);
        }
        float sum = 0.f;
#pragma unroll
        for (int p = 0; p < NTAG; p++) sum += __expf(v[p] - mx);
        float newv = mx + __logf(sum) + fcur;
        float keep = alpha[b][t];
        float nv = (s < len) ? newv : keep;
        __syncthreads();
        alpha[b][t] = nv;
        __syncthreads();
        fcur = fnext;
    }
    termS[b][t] = alpha[b][t] + tr[STOP_TAG][t];
    __syncthreads();
    if (t == 0) {
        float mx = -1e30f;
#pragma unroll
        for (int p = 0; p < NTAG; p++) mx = fmaxf(mx, termS[b][p]);
        float sum = 0.f;
#pragma unroll
        for (int p = 0; p < NTAG; p++) sum += __expf(termS[b][p] - mx);
        termS[b][0] = mx + __logf(sum);
    }
    __syncthreads();
    if (tid == 0) {
        float s2 = 0.f;
        for (int i = 0; i < 8; i++) s2 += termS[i][0];
        g_crf_part[blockIdx.x] = s2;
    }
}

__global__ void crf_finish(float* __restrict__ out) {
    float s = 0.f;
    for (int i = 0; i < 8; i++) s += g_crf_part[i];
    out[0] = s / (float)BATCH;
}

// ---------------- launch ----------------
extern "C" void kernel_launch(void* const* d_in, const int* in_sizes, int n_in,
                              void* d_out, int out_size) {
    const int*   tokens  = (const int*)  d_in[0];
    const int*   lengths = (const int*)  d_in[1];
    const float* W_emb   = (const float*)d_in[2];
    const float* W_ih_f  = (const float*)d_in[3];
    const float* W_hh_f  = (const float*)d_in[4];
    const float* b_f     = (const float*)d_in[5];
    const float* W_ih_b  = (const float*)d_in[6];
    const float* W_hh_b  = (const float*)d_in[7];
    const float* b_b     = (const float*)d_in[8];
    const float* h0      = (const float*)d_in[9];
    const float* c0      = (const float*)d_in[10];
    const float* W_out   = (const float*)d_in[11];
    const float* b_out   = (const float*)d_in[12];
    const float* trans   = (const float*)d_in[13];
    float* out = (float*)d_out;

    const int SMEM_LSTM = (32 * SWS * 2 + HID * 32) * 4;   // 196,864 B
    cudaFuncSetAttribute(lstm_persistent,
                         cudaFuncAttributeMaxDynamicSharedMemorySize, SMEM_LSTM);

    prep_kernel<<<1024, 256>>>(W_ih_f, W_ih_b, h0, W_out);
    xw_gemm<<<dim3(GATES / 128, SEQ, 2), 256>>>(tokens, W_emb, b_f, b_b);
    lstm_persistent<<<128, 512, SMEM_LSTM>>>(W_hh_f, W_hh_b, c0);
    feats_kernel<<<SEQ, 256>>>(b_out);
    crf_kernel<<<8, 96>>>(lengths, trans);
    crf_finish<<<1, 1>>>(out);
}